// round 15
// baseline (speedup 1.0000x reference)
#include <cuda_runtime.h>
#include <cuda_fp16.h>
#include <cstdint>
#include <math.h>

// Problem constants (CTCLoss_70961449664599): T=2048, B=64, V=512, S=256
#define T_DIM 2048
#define B_DIM 64
#define V_DIM 512
#define S_DIM 256
#define CHUNK 16                 // time steps staged per cp.async chunk
#define TPAD  (T_DIM + 2 * CHUNK)
#define NEG2  (-1.0e30f)
#define LOG2E_F 1.4426950408889634f
#define LN2_F   0.6931471805599453f

// Scratch (allocation-free rule: __device__ globals).
// G2[b][t][p] = half2( log2 p(symbol targets[b][p]), log2 p(blank) )
__device__ __align__(16) __half2 g_G2[(size_t)B_DIM * TPAD * S_DIM];
__device__ float g_partial[B_DIM];

__device__ __forceinline__ float ex2f_(float x) {
    float y; asm("ex2.approx.f32 %0, %1;" : "=f"(y) : "f"(x)); return y;
}
__device__ __forceinline__ float lg2f_(float x) {
    float y; asm("lg2.approx.f32 %0, %1;" : "=f"(y) : "f"(x)); return y;
}
__device__ __forceinline__ __half2 h2ex2_(__half2 x) {   // 1 MUFU, two exp2s
    unsigned int xi = *reinterpret_cast<unsigned int*>(&x), yi;
    asm("ex2.approx.f16x2 %0, %1;" : "=r"(yi) : "r"(xi));
    return *reinterpret_cast<__half2*>(&yi);
}
__device__ __forceinline__ float lse2_(float a, float b) {   // 2 MUFU
    const float m = fmaxf(a, b);
    return m + lg2f_(1.0f + ex2f_(-fabsf(a - b)));
}
// 3-term logaddexp2, 2 MUFU via f16x2 ex2 of the two non-max deltas
__device__ __forceinline__ float lse3f16_(float a0, float a1, float a2) {
    const float m01 = fmaxf(a0, a1);
    const float n01 = fminf(a0, a1);
    const float m   = fmaxf(m01, a2);
    const float s2  = fmaxf(n01, fminf(m01, a2));   // 2nd largest
    const float s3  = fminf(n01, a2);               // 3rd largest
    const __half2 he = h2ex2_(__floats2half2_rn(s2 - m, s3 - m));
    const float2 ef = __half22float2(he);
    return m + lg2f_(1.0f + ef.x + ef.y);
}
__device__ __forceinline__ unsigned int smem_u32(const void* p) {
    unsigned int a;
    asm("{ .reg .u64 t; cvta.to.shared.u64 t, %1; cvt.u32.u64 %0, t; }"
        : "=r"(a) : "l"(p));
    return a;
}

// ---------------------------------------------------------------------------
// Phase 1: log-softmax (log2 domain) + gather into half2 (symbol, blank).
// Grid: (B, T/8), block: 256 threads (8 warps, 1 warp per t-row)
// ---------------------------------------------------------------------------
__global__ __launch_bounds__(256) void ctc_phase1(
    const float* __restrict__ x, const int* __restrict__ targets)
{
    __shared__ float sh_row[8][V_DIM];
    __shared__ int   sh_tgt[S_DIM];

    const int b    = blockIdx.x;
    const int tid  = threadIdx.x;
    const int w    = tid >> 5;
    const int lane = tid & 31;

    sh_tgt[tid] = targets[b * S_DIM + tid];
    __syncthreads();

    const int t = blockIdx.y * 8 + w;
    const float4* row = (const float4*)(x + ((size_t)t * B_DIM + b) * V_DIM);

    float s = 0.0f;
    float4* shv = (float4*)sh_row[w];
#pragma unroll
    for (int k = 0; k < 4; k++) {
        float4 v = row[lane + 32 * k];
        shv[lane + 32 * k] = v;
        s += ex2f_(v.x * LOG2E_F) + ex2f_(v.y * LOG2E_F)
           + ex2f_(v.z * LOG2E_F) + ex2f_(v.w * LOG2E_F);
    }
#pragma unroll
    for (int o = 16; o; o >>= 1) s += __shfl_xor_sync(0xffffffffu, s, o);
    const float lse2v = lg2f_(s);
    const float blankv = sh_row[w][0] * LOG2E_F - lse2v;

    __half2* gout = g_G2 + ((size_t)b * TPAD + t) * S_DIM;
#pragma unroll
    for (int j = lane; j < 256; j += 32) {
        const float symv = sh_row[w][sh_tgt[j]] * LOG2E_F - lse2v;
        gout[j] = __floats2half2_rn(symv, blankv);   // .x = symbol, .y = blank
    }
}

// ---------------------------------------------------------------------------
// Phase 2: alpha recursion (log2 domain), folded register pairs, 9 warps,
// TWO time steps per __syncthreads via a 1-value halo:
//   thread p < 256 : owns positions 2p (blank) and 2p+1 (symbol) in registers
//   thread 256     : owns position 512 (blank)
// Published state per pair (every barrier): float2(even, odd).
// Halo: pair p-1's step-1 odd, recomputed locally from published values.
// ---------------------------------------------------------------------------
#define NTH 288
__global__ __launch_bounds__(NTH) void ctc_phase2(
    const int* __restrict__ targets,
    const int* __restrict__ in_len,
    const int* __restrict__ tgt_len)
{
    __shared__ __align__(16) __half2 sg[2][CHUNK * 256];  // 2 x 16 KB
    __shared__ float2 apair[2][258];   // slot 0 = pad; slot 1+q = pair q (even,odd)

    const int b   = blockIdx.x;
    const int tid = threadIdx.x;
    const int Lin = in_len[b];         // block-uniform
    const int Lt  = tgt_len[b];

    const bool mainp = (tid < 256);
    const bool act   = (tid <= 256);
    const int  p     = mainp ? tid : 255;       // own G column (t512: blank of 255)
    const int  hcol  = (tid >= 1) ? tid - 1 : 0; // halo pair index / G column

    // allow2 for own pair p and halo pair hcol (symbols >= 1: repeat check only)
    const int tp   = targets[b * S_DIM + p];
    const int tpm  = (p > 0) ? targets[b * S_DIM + p - 1] : 0;
    const bool allow2 = (tp != tpm);                      // own (mainp only)
    const int th   = targets[b * S_DIM + hcol];
    const int thm  = (hcol > 0) ? targets[b * S_DIM + hcol - 1] : 0;
    const bool allow2h = (th != thm);                     // halo pair

    const __half2* gb2 = g_G2 + (size_t)b * TPAD * S_DIM;

    // t = 0 init: only positions 0 (blank), 1 (symbol 0) live
    float a_e = NEG2, a_o = NEG2;
    if (tid == 0) {
        const __half2 g0 = __ldg(gb2);
        a_e = __high2float(g0);
        a_o = __low2float(g0);
    }
    if (act) apair[0][1 + tid] = make_float2(a_e, mainp ? a_o : NEG2);
    if (tid < 2) {
        apair[0][0] = make_float2(NEG2, NEG2);
        apair[1][0] = make_float2(NEG2, NEG2);
    }

    const unsigned int sd0 = smem_u32(&sg[0][0]);
    const unsigned int sd1 = smem_u32(&sg[1][0]);

    auto stage = [&](int c) {
        const char* src = (const char*)(gb2 + (size_t)(1 + c * CHUNK) * 256);
        const unsigned int dst = (c & 1) ? sd1 : sd0;
#pragma unroll
        for (int k = 0; k < 4; k++) {          // 1024 uint4 per chunk
            const int e = tid + k * NTH;
            if (e < CHUNK * 256 / 4) {
                asm volatile("cp.async.cg.shared.global [%0], [%1], 16;"
                             :: "r"(dst + e * 16), "l"(src + (size_t)e * 16));
            }
        }
        asm volatile("cp.async.commit_group;");
    };

    stage(0);
    const int nsteps = Lin - 1;
    const int nch = (nsteps + CHUNK - 1) / CHUNK;

    int cur = 0;
    for (int c = 0; c < nch; c++) {
        stage(c + 1);
        asm volatile("cp.async.wait_group 1;");
        __syncthreads();

        const __half2* sb = sg[c & 1];
        const int tmax = min(CHUNK, nsteps - c * CHUNK);   // block-uniform
        for (int k = 0; k < tmax; ) {
            const bool two = (k + 1 < tmax);               // block-uniform
            if (act) {
                const float2 L1 = apair[cur][tid];    // pair tid-1: (e(2t-2), o(2t-1))
                const float2 L2 = apair[cur][hcol];   // pair tid-2 (pad-safe)
                const __half2 h1 = sb[k * 256 + p];
                const float gs1 = __low2float(h1);
                const float gb1 = __high2float(h1);
                if (two) {
                    // halo: pair (tid-1) step-1 odd value
                    float h_o = NEG2;
                    if (tid >= 1) {
                        const float gsh = __low2float(sb[k * 256 + hcol]);
                        h_o = lse3f16_(L1.y, L1.x, allow2h ? L2.y : NEG2) + gsh;
                    }
                    const __half2 h2 = sb[(k + 1) * 256 + p];
                    const float gs2 = __low2float(h2);
                    const float gb2v = __high2float(h2);
                    if (mainp) {
                        const float n_e = lse2_(a_e, L1.y) + gb1;
                        const float n_o = lse3f16_(a_o, a_e,
                                                   allow2 ? L1.y : NEG2) + gs1;
                        a_e = lse2_(n_e, h_o) + gb2v;
                        a_o = lse3f16_(n_o, n_e, allow2 ? h_o : NEG2) + gs2;
                    } else {
                        const float n_x = lse2_(a_e, L1.y) + gb1;
                        a_e = lse2_(n_x, h_o) + gb2v;     // position 512
                    }
                } else {
                    if (mainp) {
                        const float n_e = lse2_(a_e, L1.y) + gb1;
                        const float n_o = lse3f16_(a_o, a_e,
                                                   allow2 ? L1.y : NEG2) + gs1;
                        a_e = n_e; a_o = n_o;
                    } else {
                        a_e = lse2_(a_e, L1.y) + gb1;
                    }
                }
                apair[cur ^ 1][1 + tid] = make_float2(a_e, mainp ? a_o : NEG2);
            }
            __syncthreads();
            cur ^= 1;
            k += two ? 2 : 1;
        }
    }

    if (tid == 0) {
        // alpha(2Lt) = even of pair Lt; alpha(2Lt-1) = odd of pair Lt-1
        const float ae = apair[cur][1 + Lt].x;
        const float ao = apair[cur][Lt].y;
        const float la2 = lse2_(ae, ao);
        float loss = -la2 * LN2_F;
        if (!isfinite(loss) || loss > 0.5e30f) loss = 0.0f;   // zero_infinity
        g_partial[b] = loss / (float)Lt;
    }
}

// ---------------------------------------------------------------------------
// Phase 3: mean over batch -> out[0]
// ---------------------------------------------------------------------------
__global__ void ctc_phase3(float* __restrict__ out)
{
    const int lane = threadIdx.x;
    float v = g_partial[lane] + g_partial[lane + 32];
#pragma unroll
    for (int o = 16; o; o >>= 1) v += __shfl_xor_sync(0xffffffffu, v, o);
    if (lane == 0) out[0] = v / (float)B_DIM;
}

// ---------------------------------------------------------------------------
extern "C" void kernel_launch(void* const* d_in, const int* in_sizes, int n_in,
                              void* d_out, int out_size)
{
    const float* x    = (const float*)d_in[0];   // (T, B, V) float32
    const int*   tgt  = (const int*)d_in[1];     // (B, S) int32
    const int*   ilen = (const int*)d_in[2];     // (B,) int32
    const int*   tlen = (const int*)d_in[3];     // (B,) int32
    float*       out  = (float*)d_out;

    dim3 g1(B_DIM, T_DIM / 8);
    ctc_phase1<<<g1, 256>>>(x, tgt);
    ctc_phase2<<<B_DIM, NTH>>>(tgt, ilen, tlen);
    ctc_phase3<<<1, 32>>>(out);
}

// round 16
// speedup vs baseline: 1.1318x; 1.1318x over previous
#include <cuda_runtime.h>
#include <cuda_fp16.h>
#include <cstdint>
#include <math.h>

// Problem constants (CTCLoss_70961449664599): T=2048, B=64, V=512, S=256
#define T_DIM 2048
#define B_DIM 64
#define V_DIM 512
#define S_DIM 256
#define CHUNK 16                 // time steps staged per cp.async chunk
#define TPAD  (T_DIM + 2 * CHUNK)
#define NEG2  (-1.0e30f)
#define LOG2E_F 1.4426950408889634f
#define LN2_F   0.6931471805599453f

// Scratch (allocation-free rule: __device__ globals).
// G2[b][t][p] = half2( log2 p(symbol targets[b][p]), log2 p(blank) )
__device__ __align__(16) __half2 g_G2[(size_t)B_DIM * TPAD * S_DIM];
__device__ float g_partial[B_DIM];

__device__ __forceinline__ float ex2f_(float x) {
    float y; asm("ex2.approx.f32 %0, %1;" : "=f"(y) : "f"(x)); return y;
}
__device__ __forceinline__ float lg2f_(float x) {
    float y; asm("lg2.approx.f32 %0, %1;" : "=f"(y) : "f"(x)); return y;
}
__device__ __forceinline__ __half2 h2ex2_(__half2 x) {   // 1 MUFU, two exp2s
    unsigned int xi = *reinterpret_cast<unsigned int*>(&x), yi;
    asm("ex2.approx.f16x2 %0, %1;" : "=r"(yi) : "r"(xi));
    return *reinterpret_cast<__half2*>(&yi);
}
__device__ __forceinline__ float lse2_(float a, float b) {   // 2 MUFU
    const float m = fmaxf(a, b);
    return m + lg2f_(1.0f + ex2f_(-fabsf(a - b)));
}
// 3-term logaddexp2, 2 MUFU via f16x2 ex2 of the two non-max deltas
__device__ __forceinline__ float lse3f16_(float a0, float a1, float a2) {
    const float m01 = fmaxf(a0, a1);
    const float n01 = fminf(a0, a1);
    const float m   = fmaxf(m01, a2);
    const float s2  = fmaxf(n01, fminf(m01, a2));   // 2nd largest
    const float s3  = fminf(n01, a2);               // 3rd largest
    const __half2 he = h2ex2_(__floats2half2_rn(s2 - m, s3 - m));
    const float2 ef = __half22float2(he);
    return m + lg2f_(1.0f + ef.x + ef.y);
}
__device__ __forceinline__ unsigned int smem_u32(const void* p) {
    unsigned int a;
    asm("{ .reg .u64 t; cvta.to.shared.u64 t, %1; cvt.u32.u64 %0, t; }"
        : "=r"(a) : "l"(p));
    return a;
}

// ---------------------------------------------------------------------------
// Phase 1: log-softmax (log2 domain) + gather into half2 (symbol, blank).
// Grid: (B, T/8), block: 256 threads (8 warps, 1 warp per t-row)
// ---------------------------------------------------------------------------
__global__ __launch_bounds__(256) void ctc_phase1(
    const float* __restrict__ x, const int* __restrict__ targets)
{
    __shared__ float sh_row[8][V_DIM];
    __shared__ int   sh_tgt[S_DIM];

    const int b    = blockIdx.x;
    const int tid  = threadIdx.x;
    const int w    = tid >> 5;
    const int lane = tid & 31;

    sh_tgt[tid] = targets[b * S_DIM + tid];
    __syncthreads();

    const int t = blockIdx.y * 8 + w;
    const float4* row = (const float4*)(x + ((size_t)t * B_DIM + b) * V_DIM);

    float s = 0.0f;
    float4* shv = (float4*)sh_row[w];
#pragma unroll
    for (int k = 0; k < 4; k++) {
        float4 v = row[lane + 32 * k];
        shv[lane + 32 * k] = v;
        s += ex2f_(v.x * LOG2E_F) + ex2f_(v.y * LOG2E_F)
           + ex2f_(v.z * LOG2E_F) + ex2f_(v.w * LOG2E_F);
    }
#pragma unroll
    for (int o = 16; o; o >>= 1) s += __shfl_xor_sync(0xffffffffu, s, o);
    const float lse2v = lg2f_(s);
    const float blankv = sh_row[w][0] * LOG2E_F - lse2v;

    __half2* gout = g_G2 + ((size_t)b * TPAD + t) * S_DIM;
#pragma unroll
    for (int j = lane; j < 256; j += 32) {
        const float symv = sh_row[w][sh_tgt[j]] * LOG2E_F - lse2v;
        gout[j] = __floats2half2_rn(symv, blankv);   // .x = symbol, .y = blank
    }
}

// ---------------------------------------------------------------------------
// Phase 2: alpha recursion (log2 domain), FOUR positions per thread, 5 warps.
//   thread q < 128 : owns pairs 2q (pos 4q,4q+1) and 2q+1 (pos 4q+2,4q+3),
//                    all four alphas in registers.
//   thread 128     : owns position 512 (blank).
//   threads 129..159: idle.
// Per step: 1 LDS float (neighbor top-pair odd) + 2x(lse2+lse3f16) +
// 1 STS float (own top-pair odd) + one __syncthreads.
// Pair 2q+1's left-dependency (old odd of pair 2q) stays in registers.
// G staged CHUNK steps/chunk via cp.async double buffer (proven).
// ---------------------------------------------------------------------------
#define NTH 160
__global__ __launch_bounds__(NTH) void ctc_phase2(
    const int* __restrict__ targets,
    const int* __restrict__ in_len,
    const int* __restrict__ tgt_len)
{
    __shared__ __align__(16) __half2 sg[2][CHUNK * 256];  // 2 x 16 KB
    __shared__ float rel[2][130];      // [x][0] = NEG2 pad; [x][1+q] = o1 of thread q
    __shared__ float2 sh_pair[257];    // final readout: (even, odd) per pair

    const int b   = blockIdx.x;
    const int tid = threadIdx.x;
    const int Lin = in_len[b];         // block-uniform
    const int Lt  = tgt_len[b];

    const bool mainp = (tid < 128);
    const bool t512  = (tid == 128);
    const bool act   = (tid <= 128);
    const int  q     = mainp ? tid : 127;
    const int  p0    = 2 * q;          // lower pair index
    const int  p1    = 2 * q + 1;      // upper pair index

    // allow2 flags (symbols >= 1: repeat check only)
    const int tA = targets[b * S_DIM + p0];
    const int tB = targets[b * S_DIM + p1];
    const int tP = (p0 > 0) ? targets[b * S_DIM + p0 - 1] : 0;
    const bool al0 = (tA != tP);       // pair p0 vs previous symbol
    const bool al1 = (tB != tA);       // pair p1 vs pair p0 symbol
    const bool alx = (targets[b*S_DIM+255] != targets[b*S_DIM+254]); (void)alx;

    const __half2* gb2 = g_G2 + (size_t)b * TPAD * S_DIM;

    // t = 0 init: only positions 0 (blank) and 1 (symbol 0) live
    float e0 = NEG2, o0 = NEG2, e1 = NEG2, o1 = NEG2;   // pairs p0, p1
    float a_x = NEG2;                                    // position 512 (t512)
    if (tid == 0) {
        const __half2 g0 = __ldg(gb2);
        e0 = __high2float(g0);   // pos 0 = blank
        o0 = __low2float(g0);    // pos 1 = symbol 0
    }
    if (act) rel[0][1 + tid] = mainp ? o1 : NEG2;
    if (tid < 2) { rel[0][0] = NEG2; rel[1][0] = NEG2; }

    const unsigned int sd0 = smem_u32(&sg[0][0]);
    const unsigned int sd1 = smem_u32(&sg[1][0]);

    // stage chunk c = G2 rows [1 + c*CHUNK, +CHUNK) -> sg[c&1]  (16 KB)
    auto stage = [&](int c) {
        const char* src = (const char*)(gb2 + (size_t)(1 + c * CHUNK) * 256);
        const unsigned int dst = (c & 1) ? sd1 : sd0;
#pragma unroll
        for (int k = 0; k < 7; k++) {          // 1024 uint4 total, 160 threads
            const int e = tid + k * NTH;
            if (e < CHUNK * 256 / 4) {
                asm volatile("cp.async.cg.shared.global [%0], [%1], 16;"
                             :: "r"(dst + e * 16), "l"(src + (size_t)e * 16));
            }
        }
        asm volatile("cp.async.commit_group;");
    };

    stage(0);
    const int nsteps = Lin - 1;
    const int nch = (nsteps + CHUNK - 1) / CHUNK;

    int cur = 0;
    for (int c = 0; c < nch; c++) {
        stage(c + 1);
        asm volatile("cp.async.wait_group 1;");
        __syncthreads();                       // chunk c + relay state visible

        const __half2* sb = sg[c & 1];
        const int tmax = min(CHUNK, nsteps - c * CHUNK);   // block-uniform
        for (int k = 0; k < tmax; k++) {
            if (act) {
                const float a_left = rel[cur][tid];    // old odd of pair p0-1
                if (mainp) {
                    const __half2 hA = sb[k * 256 + p0];
                    const __half2 hB = sb[k * 256 + p1];
                    const float gsA = __low2float(hA), gbA = __high2float(hA);
                    const float gsB = __low2float(hB), gbB = __high2float(hB);
                    // all four updates independent given OLD values
                    const float ne0 = lse2_(e0, a_left) + gbA;
                    const float no0 = lse3f16_(o0, e0, al0 ? a_left : NEG2) + gsA;
                    const float ne1 = lse2_(e1, o0) + gbB;
                    const float no1 = lse3f16_(o1, e1, al1 ? o0 : NEG2) + gsB;
                    e0 = ne0; o0 = no0; e1 = ne1; o1 = no1;
                    rel[cur ^ 1][1 + tid] = no1;
                } else {
                    // position 512 (blank): left = old odd of pair 255
                    a_x = lse2_(a_x, a_left) + __high2float(sb[k * 256 + 255]);
                }
            }
            __syncthreads();
            cur ^= 1;
        }
    }

    if (mainp) {
        sh_pair[p0] = make_float2(e0, o0);
        sh_pair[p1] = make_float2(e1, o1);
    } else if (t512) {
        sh_pair[256] = make_float2(a_x, NEG2);
    }
    __syncthreads();

    if (tid == 0) {
        // alpha(2Lt) = even of pair Lt; alpha(2Lt-1) = odd of pair Lt-1
        const float ae = sh_pair[Lt].x;
        const float ao = sh_pair[Lt - 1].y;
        const float la2 = lse2_(ae, ao);
        float loss = -la2 * LN2_F;
        if (!isfinite(loss) || loss > 0.5e30f) loss = 0.0f;   // zero_infinity
        g_partial[b] = loss / (float)Lt;
    }
}

// ---------------------------------------------------------------------------
// Phase 3: mean over batch -> out[0]
// ---------------------------------------------------------------------------
__global__ void ctc_phase3(float* __restrict__ out)
{
    const int lane = threadIdx.x;
    float v = g_partial[lane] + g_partial[lane + 32];
#pragma unroll
    for (int o = 16; o; o >>= 1) v += __shfl_xor_sync(0xffffffffu, v, o);
    if (lane == 0) out[0] = v / (float)B_DIM;
}

// ---------------------------------------------------------------------------
extern "C" void kernel_launch(void* const* d_in, const int* in_sizes, int n_in,
                              void* d_out, int out_size)
{
    const float* x    = (const float*)d_in[0];   // (T, B, V) float32
    const int*   tgt  = (const int*)d_in[1];     // (B, S) int32
    const int*   ilen = (const int*)d_in[2];     // (B,) int32
    const int*   tlen = (const int*)d_in[3];     // (B,) int32
    float*       out  = (float*)d_out;

    dim3 g1(B_DIM, T_DIM / 8);
    ctc_phase1<<<g1, 256>>>(x, tgt);
    ctc_phase2<<<B_DIM, NTH>>>(tgt, ilen, tlen);
    ctc_phase3<<<1, 32>>>(out);
}

// round 17
// speedup vs baseline: 1.1403x; 1.0074x over previous
#include <cuda_runtime.h>
#include <cuda_fp16.h>
#include <cstdint>
#include <math.h>

// Problem constants (CTCLoss_70961449664599): T=2048, B=64, V=512, S=256
#define T_DIM 2048
#define B_DIM 64
#define V_DIM 512
#define S_DIM 256
#define CHUNK 16                 // time steps staged per cp.async chunk
#define TPAD  (T_DIM + 2 * CHUNK)
#define NEG2  (-1.0e30f)
#define LOG2E_F 1.4426950408889634f
#define LN2_F   0.6931471805599453f

// Scratch (allocation-free rule: __device__ globals).
// G2[b][t][p] = half2( log2 p(symbol targets[b][p]), log2 p(blank) )
__device__ __align__(16) __half2 g_G2[(size_t)B_DIM * TPAD * S_DIM];
__device__ float g_partial[B_DIM];

__device__ __forceinline__ float ex2f_(float x) {
    float y; asm("ex2.approx.f32 %0, %1;" : "=f"(y) : "f"(x)); return y;
}
__device__ __forceinline__ float lg2f_(float x) {
    float y; asm("lg2.approx.f32 %0, %1;" : "=f"(y) : "f"(x)); return y;
}
__device__ __forceinline__ float lse2_(float a, float b) {   // 2 MUFU
    const float m = fmaxf(a, b);
    return m + lg2f_(1.0f + ex2f_(-fabsf(a - b)));
}
// 3-term logaddexp2, all-f32: max network + two PARALLEL ex2 + one lg2.
// Short latency chain (no f16 conversions); 3 MUFU.
__device__ __forceinline__ float lse3v2_(float a0, float a1, float a2) {
    const float m01 = fmaxf(a0, a1);
    const float n01 = fminf(a0, a1);
    const float m   = fmaxf(m01, a2);
    const float s2  = fmaxf(n01, fminf(m01, a2));   // 2nd largest
    const float s3  = fminf(n01, a2);               // 3rd largest
    return m + lg2f_(1.0f + ex2f_(s2 - m) + ex2f_(s3 - m));
}
__device__ __forceinline__ unsigned int smem_u32(const void* p) {
    unsigned int a;
    asm("{ .reg .u64 t; cvta.to.shared.u64 t, %1; cvt.u32.u64 %0, t; }"
        : "=r"(a) : "l"(p));
    return a;
}

// ---------------------------------------------------------------------------
// Phase 1: log-softmax (log2 domain) + gather into half2 (symbol, blank).
// Grid: (B, T/8), block: 256 threads (8 warps, 1 warp per t-row)
// ---------------------------------------------------------------------------
__global__ __launch_bounds__(256) void ctc_phase1(
    const float* __restrict__ x, const int* __restrict__ targets)
{
    __shared__ float sh_row[8][V_DIM];
    __shared__ int   sh_tgt[S_DIM];

    const int b    = blockIdx.x;
    const int tid  = threadIdx.x;
    const int w    = tid >> 5;
    const int lane = tid & 31;

    sh_tgt[tid] = targets[b * S_DIM + tid];
    __syncthreads();

    const int t = blockIdx.y * 8 + w;
    const float4* row = (const float4*)(x + ((size_t)t * B_DIM + b) * V_DIM);

    float s = 0.0f;
    float4* shv = (float4*)sh_row[w];
#pragma unroll
    for (int k = 0; k < 4; k++) {
        float4 v = row[lane + 32 * k];
        shv[lane + 32 * k] = v;
        s += ex2f_(v.x * LOG2E_F) + ex2f_(v.y * LOG2E_F)
           + ex2f_(v.z * LOG2E_F) + ex2f_(v.w * LOG2E_F);
    }
#pragma unroll
    for (int o = 16; o; o >>= 1) s += __shfl_xor_sync(0xffffffffu, s, o);
    const float lse2v = lg2f_(s);
    const float blankv = sh_row[w][0] * LOG2E_F - lse2v;

    __half2* gout = g_G2 + ((size_t)b * TPAD + t) * S_DIM;
#pragma unroll
    for (int j = lane; j < 256; j += 32) {
        const float symv = sh_row[w][sh_tgt[j]] * LOG2E_F - lse2v;
        gout[j] = __floats2half2_rn(symv, blankv);   // .x = symbol, .y = blank
    }
}

// ---------------------------------------------------------------------------
// Phase 2: alpha recursion (log2 domain), folded pairs, exactly 8 warps.
//   thread p : owns positions 2p (blank, reg a_e) and 2p+1 (symbol, reg a_o)
//   thread 255 additionally owns position 512 (blank, reg a_x) — the blank
//   log-prob is column-independent, so its G value is already in h.
// Per step: 1 LDS relay + 1 LDS G pair + lse2 + lse3v2 + 1 STS + 1 barrier.
// G staged CHUNK steps/chunk via cp.async double buffer (proven).
// ---------------------------------------------------------------------------
#define NTH 256
__global__ __launch_bounds__(NTH) void ctc_phase2(
    const int* __restrict__ targets,
    const int* __restrict__ in_len,
    const int* __restrict__ tgt_len)
{
    __shared__ __align__(16) __half2 sg[2][CHUNK * 256];  // 2 x 16 KB
    __shared__ float rel[2][258];   // [x][0] = NEG2 pad; [x][1+p] = odd of pair p
    __shared__ float sh_e[257];     // readout: final even alphas (+ pos 512)

    const int b   = blockIdx.x;
    const int tid = threadIdx.x;
    const int Lin = in_len[b];      // block-uniform
    const int Lt  = tgt_len[b];
    const bool last = (tid == 255);

    const int curt  = targets[b * S_DIM + tid];
    const int prevt = (tid > 0) ? targets[b * S_DIM + tid - 1] : 0;
    const bool allow2 = (curt != prevt);   // symbols >= 1, repeat check only

    const __half2* gb2 = g_G2 + (size_t)b * TPAD * S_DIM;

    // t = 0 init: only positions 0 (blank) and 1 (symbol 0) live
    float a_e = NEG2, a_o = NEG2, a_x = NEG2;
    if (tid == 0) {
        const __half2 g0 = __ldg(gb2);
        a_e = __high2float(g0);
        a_o = __low2float(g0);
    }
    rel[0][1 + tid] = a_o;
    if (tid < 2) { rel[0][0] = NEG2; rel[1][0] = NEG2; }

    const unsigned int sd0 = smem_u32(&sg[0][0]);
    const unsigned int sd1 = smem_u32(&sg[1][0]);

    // stage chunk c = G2 rows [1 + c*CHUNK, +CHUNK) -> sg[c&1]  (16 KB)
    auto stage = [&](int c) {
        const char* src = (const char*)(gb2 + (size_t)(1 + c * CHUNK) * 256);
        const unsigned int dst = (c & 1) ? sd1 : sd0;
#pragma unroll
        for (int k = 0; k < 4; k++) {          // 256 threads x 4 x 16B = 16 KB
            const int e = tid + k * NTH;
            asm volatile("cp.async.cg.shared.global [%0], [%1], 16;"
                         :: "r"(dst + e * 16), "l"(src + (size_t)e * 16));
        }
        asm volatile("cp.async.commit_group;");
    };

    stage(0);
    const int nsteps = Lin - 1;
    const int nch = (nsteps + CHUNK - 1) / CHUNK;

    int cur = 0;
    for (int c = 0; c < nch; c++) {
        stage(c + 1);
        asm volatile("cp.async.wait_group 1;");
        __syncthreads();                       // chunk c + relay state visible

        const __half2* sb = sg[c & 1];
        const int tmax = min(CHUNK, nsteps - c * CHUNK);   // block-uniform
        for (int k = 0; k < tmax; k++) {
            const float a_left = rel[cur][tid];        // old alpha(2p-1)
            const __half2 h = sb[k * 256 + tid];
            const float gs  = __low2float(h);
            const float gbl = __high2float(h);
            const float ne = lse2_(a_e, a_left) + gbl;
            const float no = lse3v2_(a_o, a_e, allow2 ? a_left : NEG2) + gs;
            if (last) a_x = lse2_(a_x, a_o) + gbl;     // pos 512, uses OLD a_o
            a_e = ne; a_o = no;
            rel[cur ^ 1][1 + tid] = no;
            __syncthreads();
            cur ^= 1;
        }
    }

    sh_e[tid] = a_e;
    if (last) sh_e[256] = a_x;
    __syncthreads();

    if (tid == 0) {
        // alpha(2Lt) = even of pair Lt (or pos 512 for Lt=256);
        // alpha(2Lt-1) = odd of pair Lt-1 = rel[cur][Lt]
        const float ae = sh_e[Lt];
        const float ao = rel[cur][Lt];
        const float la2 = lse2_(ae, ao);
        float loss = -la2 * LN2_F;
        if (!isfinite(loss) || loss > 0.5e30f) loss = 0.0f;   // zero_infinity
        g_partial[b] = loss / (float)Lt;
    }
}

// ---------------------------------------------------------------------------
// Phase 3: mean over batch -> out[0]
// ---------------------------------------------------------------------------
__global__ void ctc_phase3(float* __restrict__ out)
{
    const int lane = threadIdx.x;
    float v = g_partial[lane] + g_partial[lane + 32];
#pragma unroll
    for (int o = 16; o; o >>= 1) v += __shfl_xor_sync(0xffffffffu, v, o);
    if (lane == 0) out[0] = v / (float)B_DIM;
}

// ---------------------------------------------------------------------------
extern "C" void kernel_launch(void* const* d_in, const int* in_sizes, int n_in,
                              void* d_out, int out_size)
{
    const float* x    = (const float*)d_in[0];   // (T, B, V) float32
    const int*   tgt  = (const int*)d_in[1];     // (B, S) int32
    const int*   ilen = (const int*)d_in[2];     // (B,) int32
    const int*   tlen = (const int*)d_in[3];     // (B,) int32
    float*       out  = (float*)d_out;

    dim3 g1(B_DIM, T_DIM / 8);
    ctc_phase1<<<g1, 256>>>(x, tgt);
    ctc_phase2<<<B_DIM, NTH>>>(tgt, ilen, tlen);
    ctc_phase3<<<1, 32>>>(out);
}